// round 16
// baseline (speedup 1.0000x reference)
#include <cuda_runtime.h>
#include <cuda_fp16.h>
#include <math.h>
#include <stdint.h>

// ---------------------------------------------------------------------------
// Problem constants
// ---------------------------------------------------------------------------
#define NB   4
#define C1   256
#define CM   128
#define C2   256
#define HW   4096
#define NPIX (NB*HW)
#define PP   9
#define BN_EPS 1e-5f
#define LN_EPS 1e-6f

typedef __half hlf;

// ---------------------------------------------------------------------------
// Scratch (offsets in floats)
// ---------------------------------------------------------------------------
#define OFF_XHI   0                          // NPIX*C1 fp16
#define OFF_Y1HI  (OFF_XHI  + NPIX*C1/2)     // NPIX*CM fp16
#define OFF_Y2HI  (OFF_Y1HI + NPIX*CM/2)     // NPIX*C2 fp16
#define OFF_X1HI  (OFF_Y2HI + NPIX*C2/2)     // NPIX*C2 fp16
#define OFF_XPROJ (OFF_X1HI + NPIX*C2/2)     // fp16
#define OFF_OM    (OFF_XPROJ+ NPIX*C2/2)
#define OFF_CHI   (OFF_OM   + NPIX*27)       // fp16
#define OFF_ONH   (OFF_CHI  + NPIX*C2/2)     // f32 NHWC out_proj result
#define OFF_WT9H  (OFF_ONH  + NPIX*C2)       // 9*128*256 fp16 [tap][co][ci]
#define OFF_PWH   (OFF_WT9H + 9*CM*C1/2)
#define OFF_INH   (OFF_PWH  + C2*CM/2)
#define OFF_OUH   (OFF_INH  + C2*C2/2)
#define OFF_HWH   (OFF_OUH  + C2*C2/2)       // 32*256 fp16 head weights
#define OFF_HB    (OFF_HWH  + 32*C2/2)       // 32 f32 head bias
#define SCRATCH_FLOATS (OFF_HB + 32)

__device__ __align__(16) float g_scratch[SCRATCH_FLOATS];

__device__ __forceinline__ float silu(float v) { return v / (1.0f + expf(-v)); }

__device__ __forceinline__ uint32_t pack_h2(float a, float b) {
    hlf ha = __float2half_rn(a), hb = __float2half_rn(b);
    return ((uint32_t)*(uint16_t*)&hb << 16) | *(uint16_t*)&ha;
}

// ---------------------------------------------------------------------------
// mma.sync + ldmatrix + cp.async (portable sm_80 PTX)
// ---------------------------------------------------------------------------
__device__ __forceinline__ void mma16816(float* d, const uint32_t* a, const uint32_t* b) {
    asm volatile("mma.sync.aligned.m16n8k16.row.col.f32.f16.f16.f32 "
        "{%0,%1,%2,%3}, {%4,%5,%6,%7}, {%8,%9}, {%0,%1,%2,%3};"
        : "+f"(d[0]), "+f"(d[1]), "+f"(d[2]), "+f"(d[3])
        : "r"(a[0]), "r"(a[1]), "r"(a[2]), "r"(a[3]), "r"(b[0]), "r"(b[1]));
}
__device__ __forceinline__ void ldm4(uint32_t* r, uint32_t addr) {
    asm volatile("ldmatrix.sync.aligned.m8n8.x4.shared.b16 {%0,%1,%2,%3}, [%4];"
        : "=r"(r[0]), "=r"(r[1]), "=r"(r[2]), "=r"(r[3]) : "r"(addr));
}
__device__ __forceinline__ void cp16(uint32_t dst, const void* src) {
    asm volatile("cp.async.cg.shared.global [%0], [%1], 16;" :: "r"(dst), "l"(src));
}
__device__ __forceinline__ void cp16z(uint32_t dst, const void* src, int srcsize) {
    asm volatile("cp.async.cg.shared.global [%0], [%1], 16, %2;"
                 :: "r"(dst), "l"(src), "r"(srcsize));
}
#define CP_COMMIT() asm volatile("cp.async.commit_group;" ::: "memory")
#define CP_WAIT2()  asm volatile("cp.async.wait_group 2;" ::: "memory")

// SMEM row: 32 fp16 = 16 words, padded to 20 (conflict-free for ldmatrix)
#define TS 20
#define AW  (64 * TS)
#define BW  (128 * TS)
#define CONV_STW (AW + BW)
#define CONV_SMEM (4 * CONV_STW * 4)        // 4-stage ring
#define GEMM_STW1 (AW + BW)
#define GEMM_SMEM1 (4 * GEMM_STW1 * 4)      // 4-stage ring

// ---------------------------------------------------------------------------
// prep_x: NCHW f32 -> NHWC fp16
// ---------------------------------------------------------------------------
__global__ __launch_bounds__(256) void prep_x_k(
    const float* __restrict__ x, hlf* __restrict__ xhi)
{
    __shared__ float t[32][33];
    const int n = blockIdx.z, hw0 = blockIdx.x * 32, c0 = blockIdx.y * 32;
    const int tx = threadIdx.x & 31, ty = threadIdx.x >> 5;
#pragma unroll
    for (int i = ty; i < 32; i += 8)
        t[i][tx] = x[((size_t)n * C1 + c0 + i) * HW + hw0 + tx];
    __syncthreads();
#pragma unroll
    for (int i = ty; i < 32; i += 8) {
        size_t idx = ((size_t)n * HW + hw0 + i) * C1 + c0 + tx;
        xhi[idx] = __float2half_rn(t[tx][i]);
    }
}

// ---------------------------------------------------------------------------
// prep_w: all weights -> fp16; cv1 -> [tap][co][ci]; head pack
// ---------------------------------------------------------------------------
__global__ __launch_bounds__(256) void prep_w_k(
    const float* __restrict__ cv1w, const float* __restrict__ pww,
    const float* __restrict__ inpw, const float* __restrict__ outw,
    const float* __restrict__ offw, const float* __restrict__ mskw,
    const float* __restrict__ offb, const float* __restrict__ mskb,
    hlf* __restrict__ wt9h, hlf* __restrict__ pwh,
    hlf* __restrict__ inh,  hlf* __restrict__ ouh,
    hlf* __restrict__ hwh,  float* __restrict__ hb)
{
    int idx = blockIdx.x * 256 + threadIdx.x;
    const int N1 = 9 * CM * C1;
    if (idx < N1) {
        int tap = idx / (CM * C1);
        int rem = idx - tap * CM * C1;
        int co = rem >> 8, ci = rem & 255;
        wt9h[idx] = __float2half_rn(cv1w[(size_t)co * (C1 * 9) + ci * 9 + tap]);
        return;
    }
    idx -= N1;
    if (idx < C2 * CM) { pwh[idx] = __float2half_rn(pww[idx]); return; }
    idx -= C2 * CM;
    if (idx < C2 * C2) { inh[idx] = __float2half_rn(inpw[idx]); return; }
    idx -= C2 * C2;
    if (idx < C2 * C2) { ouh[idx] = __float2half_rn(outw[idx]); return; }
    idx -= C2 * C2;
    if (idx < 32 * C2) {
        int j = idx >> 8, k = idx & 255;
        float v = (j < 18) ? offw[j * C2 + k] : ((j < 27) ? mskw[(j - 18) * C2 + k] : 0.0f);
        hwh[idx] = __float2half_rn(v); return;
    }
    idx -= 32 * C2;
    if (idx < 32)
        hb[idx] = (idx < 18) ? offb[idx] : ((idx < 27) ? mskb[idx - 18] : 0.0f);
}

// ---------------------------------------------------------------------------
// Inner MMA via ldmatrix. A tile 64x32 (fp16), B tile 128x32.
// ---------------------------------------------------------------------------
__device__ __forceinline__ void mma_step1(
    uint32_t aHi, uint32_t bHi, int wm, int wn, int lane, float acc[2][4][4])
{
    const int arow = (lane & 7) + ((lane >> 3) & 1) * 8;
    const int akt  = (lane >> 4) & 1;
    const int brow = (lane & 7) + ((lane >> 4) & 1) * 8;
    const int bkt  = (lane >> 3) & 1;
#pragma unroll
    for (int ks = 0; ks < 2; ks++) {
        uint32_t ahi[2][4], bhi[2][4];
#pragma unroll
        for (int mt = 0; mt < 2; mt++) {
            uint32_t off = (uint32_t)(((wm * 32 + mt * 16 + arow) * TS + ks * 8 + akt * 4) * 4);
            ldm4(ahi[mt], aHi + off);
        }
#pragma unroll
        for (int np = 0; np < 2; np++) {
            uint32_t off = (uint32_t)(((wn * 32 + np * 16 + brow) * TS + ks * 8 + bkt * 4) * 4);
            ldm4(bhi[np], bHi + off);
        }
#pragma unroll
        for (int mt = 0; mt < 2; mt++)
#pragma unroll
            for (int nt = 0; nt < 4; nt++)
                mma16816(acc[mt][nt], ahi[mt], &bhi[nt >> 1][(nt & 1) * 2]);
    }
}

// ---------------------------------------------------------------------------
// mma_conv: cv1 3x3 (256->128) + BN + SiLU. 1-term fp16, 4-stage single-sync.
// ---------------------------------------------------------------------------
__global__ __launch_bounds__(256, 2) void mma_conv_k(
    const hlf* __restrict__ xhi, const hlf* __restrict__ wth,
    const float* __restrict__ g, const float* __restrict__ b,
    hlf* __restrict__ y1hi)
{
    extern __shared__ __align__(16) uint32_t dsm[];
    const uint32_t sbase = (uint32_t)__cvta_generic_to_shared(dsm);

    const int tid = threadIdx.x, wid = tid >> 5, lane = tid & 31;
    const int wm = wid >> 2, wn = wid & 3, qr = lane >> 2, qc = lane & 3;
    const int pix0 = blockIdx.x * 64;
    const int n = pix0 >> 12, hb2 = (pix0 & 4095) >> 6;
    const int r0 = tid >> 2, ch0 = tid & 3;

    float acc[2][4][4];
#pragma unroll
    for (int mt = 0; mt < 2; mt++)
#pragma unroll
        for (int nt = 0; nt < 4; nt++)
#pragma unroll
            for (int q = 0; q < 4; q++) acc[mt][nt][q] = 0.0f;

    const int TOT = 72;
    auto stage = [&](int it) {
        const int tap = it / 8, kc = it & 7;
        const int dh = tap / 3 - 1, dw = tap % 3 - 1;
        const uint32_t sb = sbase + (uint32_t)(it & 3) * (CONV_STW * 4);
        {
            int hh = hb2 + dh, ww = r0 + dw;
            bool val = ((unsigned)hh < 64u) && ((unsigned)ww < 64u);
            size_t u4 = val ? ((size_t)(n * HW + hh * 64 + ww) * 32 + kc * 4 + ch0) : 0;
            int sz = val ? 16 : 0;
            uint32_t rowoff = (uint32_t)(r0 * TS + ch0 * 4) * 4;
            cp16z(sb + rowoff, (const char*)xhi + u4 * 16, sz);
        }
#pragma unroll
        for (int i = 0; i < 2; i++) {
            int r = r0 + i * 64;
            size_t w4 = (size_t)(tap * CM + r) * 32 + kc * 4 + ch0;
            uint32_t rowoff = (uint32_t)(r * TS + ch0 * 4) * 4;
            cp16(sb + AW * 4 + rowoff, (const char*)wth + w4 * 16);
        }
    };

    stage(0); CP_COMMIT();
    stage(1); CP_COMMIT();
    for (int it = 0; it < TOT; it++) {
        if (it + 2 < TOT) stage(it + 2);
        CP_COMMIT();
        CP_WAIT2();
        __syncthreads();
        uint32_t sb = sbase + (uint32_t)(it & 3) * (CONV_STW * 4);
        mma_step1(sb, sb + AW * 4, wm, wn, lane, acc);
    }

#pragma unroll
    for (int nt = 0; nt < 4; nt++) {
        int c = wn * 32 + nt * 8 + qc * 2;
        float s0 = g[c] * rsqrtf(1.0f + BN_EPS),     b0 = b[c];
        float s1 = g[c + 1] * rsqrtf(1.0f + BN_EPS), b1 = b[c + 1];
#pragma unroll
        for (int mt = 0; mt < 2; mt++) {
            int row = wm * 32 + mt * 16 + qr;
#pragma unroll
            for (int half = 0; half < 2; half++) {
                int pix = pix0 + row + half * 8;
                float v0 = silu(fmaf(acc[mt][nt][half * 2 + 0], s0, b0));
                float v1 = silu(fmaf(acc[mt][nt][half * 2 + 1], s1, b1));
                *(uint32_t*)&y1hi[(size_t)pix * CM + c] = pack_h2(v0, v1);
            }
        }
    }
}

// ---------------------------------------------------------------------------
// mma_gemm: C[M,256] = A[M,K](fp16) @ Wfp16[256,K]^T. 4-stage single-sync.
// One block covers 64 pixels x full N=256 via in-block N-half loop (1 wave).
// MODE 0: BN+SiLU -> fp16.  MODE 1: +bias -> f32 NHWC.  MODE 2: +bias -> fp16.
// ---------------------------------------------------------------------------
template<int K, int MODE>
__global__ __launch_bounds__(256, 2) void mma_gemm_k(
    const hlf* __restrict__ Ahi, const hlf* __restrict__ Whi,
    const float* __restrict__ p0, const float* __restrict__ p1,
    float* __restrict__ outf, hlf* __restrict__ outhi)
{
    extern __shared__ __align__(16) uint32_t dsm[];
    const uint32_t sbase = (uint32_t)__cvta_generic_to_shared(dsm);
    constexpr int STW = AW + BW;

    const int tid = threadIdx.x, wid = tid >> 5, lane = tid & 31;
    const int wm = wid >> 2, wn = wid & 3, qr = lane >> 2, qc = lane & 3;
    const int pix0 = blockIdx.x * 64;
    const int r0 = tid >> 2, ch0 = tid & 3;

    constexpr int NIT = K / 32;
    constexpr int TOT = 2 * NIT;          // two N-halves

    float acc[2][4][4];
#pragma unroll
    for (int mt = 0; mt < 2; mt++)
#pragma unroll
        for (int nt = 0; nt < 4; nt++)
#pragma unroll
            for (int q = 0; q < 4; q++) acc[mt][nt][q] = 0.0f;

    auto stage = [&](int it) {
        const int nh = it / NIT, kc = it % NIT;
        const uint32_t sb = sbase + (uint32_t)(it & 3) * (STW * 4);
        {
            size_t a4 = (size_t)(pix0 + r0) * (K / 8) + kc * 4 + ch0;
            uint32_t rowoff = (uint32_t)(r0 * TS + ch0 * 4) * 4;
            cp16(sb + rowoff, (const char*)Ahi + a4 * 16);
        }
#pragma unroll
        for (int i = 0; i < 2; i++) {
            int r = r0 + i * 64;
            size_t b4 = (size_t)(nh * 128 + r) * (K / 8) + kc * 4 + ch0;
            uint32_t rowoff = (uint32_t)(r * TS + ch0 * 4) * 4;
            cp16(sb + AW * 4 + rowoff, (const char*)Whi + b4 * 16);
        }
    };

    stage(0); CP_COMMIT();
    stage(1); CP_COMMIT();
    for (int it = 0; it < TOT; it++) {
        if (it + 2 < TOT) stage(it + 2);
        CP_COMMIT();
        CP_WAIT2();
        __syncthreads();
        uint32_t sb = sbase + (uint32_t)(it & 3) * (STW * 4);
        mma_step1(sb, sb + AW * 4, wm, wn, lane, acc);

        if ((it + 1) % NIT == 0) {
            // ---- epilogue for N-half nh ----
            const int nh = it / NIT;
#pragma unroll
            for (int nt = 0; nt < 4; nt++) {
                int c = nh * 128 + wn * 32 + nt * 8 + qc * 2;
                float s0, b0, s1, b1;
                if (MODE == 0) {
                    s0 = p0[c] * rsqrtf(1.0f + BN_EPS);     b0 = p1[c];
                    s1 = p0[c + 1] * rsqrtf(1.0f + BN_EPS); b1 = p1[c + 1];
                } else {
                    b0 = p0[c]; b1 = p0[c + 1]; s0 = s1 = 1.0f;
                }
#pragma unroll
                for (int mt = 0; mt < 2; mt++) {
                    int row = wm * 32 + mt * 16 + qr;
#pragma unroll
                    for (int half = 0; half < 2; half++) {
                        int pix = pix0 + row + half * 8;
                        if (MODE == 0) {
                            float v0 = silu(fmaf(acc[mt][nt][half * 2 + 0], s0, b0));
                            float v1 = silu(fmaf(acc[mt][nt][half * 2 + 1], s1, b1));
                            *(uint32_t*)&outhi[(size_t)pix * C2 + c] = pack_h2(v0, v1);
                        } else if (MODE == 1) {
                            float v0 = acc[mt][nt][half * 2 + 0] + b0;
                            float v1 = acc[mt][nt][half * 2 + 1] + b1;
                            *(float2*)&outf[(size_t)pix * C2 + c] = make_float2(v0, v1);
                        } else {
                            float v0 = acc[mt][nt][half * 2 + 0] + b0;
                            float v1 = acc[mt][nt][half * 2 + 1] + b1;
                            *(uint32_t*)&outhi[(size_t)pix * C2 + c] = pack_h2(v0, v1);
                        }
                    }
                }
            }
#pragma unroll
            for (int mt = 0; mt < 2; mt++)
#pragma unroll
                for (int nt = 0; nt < 4; nt++)
#pragma unroll
                    for (int q = 0; q < 4; q++) acc[mt][nt][q] = 0.0f;
        }
    }
}

// ---------------------------------------------------------------------------
// mma_head: om[M,27] = x1hi[M,256] @ HW16[32,256]^T + hb (1-term fp16).
// ---------------------------------------------------------------------------
#define BS2 132
#define HEAD_SMEM ((128*TS + 32*BS2) * 4)
__global__ __launch_bounds__(256) void mma_head_k(
    const hlf* __restrict__ x1hi, const hlf* __restrict__ hwh,
    const float* __restrict__ hb, float* __restrict__ om)
{
    extern __shared__ __align__(16) uint32_t dsm[];
    const uint32_t sbase = (uint32_t)__cvta_generic_to_shared(dsm);
    const uint32_t AHI = 0, BHI = 128 * TS;

    const int tid = threadIdx.x, wid = tid >> 5, lane = tid & 31;
    const int pix0 = blockIdx.x * 128;

    for (int i = tid; i < 1024; i += 256) {
        int row = i >> 5, ch = i & 31;
        *(uint4*)&dsm[BHI + row * BS2 + ch * 4] = ((const uint4*)hwh)[row * 32 + ch];
    }

    float acc[4][4];
#pragma unroll
    for (int nt = 0; nt < 4; nt++)
#pragma unroll
        for (int q = 0; q < 4; q++) acc[nt][q] = 0.0f;

    const int arow = (lane & 7) + ((lane >> 3) & 1) * 8;
    const int akt  = (lane >> 4) & 1;
    const int brow = (lane & 7) + ((lane >> 4) & 1) * 8;
    const int bkt  = (lane >> 3) & 1;

    for (int kc = 0; kc < 8; kc++) {
        __syncthreads();
        for (int i = tid; i < 512; i += 256) {
            int row = i >> 2, ch = i & 3;
            const uint4 v = ((const uint4*)x1hi)[(size_t)(pix0 + row) * 32 + kc * 4 + ch];
            *(uint4*)&dsm[AHI + row * TS + ch * 4] = v;
        }
        __syncthreads();
#pragma unroll
        for (int ks = 0; ks < 2; ks++) {
            uint32_t ahi[4], bhi[2][4];
            uint32_t aoff = (uint32_t)(((wid * 16 + arow) * TS + ks * 8 + akt * 4) * 4);
            ldm4(ahi, sbase + AHI * 4 + aoff);
#pragma unroll
            for (int np = 0; np < 2; np++) {
                uint32_t boff = (uint32_t)(((np * 16 + brow) * BS2 + kc * 16 + ks * 8 + bkt * 4) * 4);
                ldm4(bhi[np], sbase + BHI * 4 + boff);
            }
#pragma unroll
            for (int nt = 0; nt < 4; nt++)
                mma16816(acc[nt], ahi, &bhi[nt >> 1][(nt & 1) * 2]);
        }
    }

#pragma unroll
    for (int nt = 0; nt < 4; nt++) {
        int c = nt * 8 + (lane & 3) * 2;
        int r0p = pix0 + wid * 16 + (lane >> 2);
#pragma unroll
        for (int half = 0; half < 2; half++) {
            int pix = r0p + half * 8;
            float v0 = acc[nt][half * 2 + 0] + hb[c];
            float v1 = acc[nt][half * 2 + 1] + hb[c + 1];
            if (c < 27)     om[(size_t)pix * 27 + c]     = v0;
            if (c + 1 < 27) om[(size_t)pix * 27 + c + 1] = v1;
        }
    }
}

// ---------------------------------------------------------------------------
// Fused: depthwise 3x3 (fp16 y2hi, half2) + LN + GELU -> x1hi
// ---------------------------------------------------------------------------
__global__ __launch_bounds__(128) void dw_ln_gelu_k(
    const hlf* __restrict__ y2h,
    const float* __restrict__ dww, const float* __restrict__ dwb,
    const float* __restrict__ lg,  const float* __restrict__ lb,
    hlf* __restrict__ x1hi)
{
    const int pix = blockIdx.x;
    const int n = pix >> 12, hw = pix & 4095, h = hw >> 6, w = hw & 63;
    const int t = threadIdx.x;
    const int c = t * 2;

    float v0 = dwb[c], v1 = dwb[c + 1];
#pragma unroll
    for (int kh = 0; kh < 3; kh++)
#pragma unroll
        for (int kw = 0; kw < 3; kw++) {
            int hh = h + kh - 1, wk = w + kw - 1;
            if ((unsigned)hh < 64u && (unsigned)wk < 64u) {
                __half2 y = *(const __half2*)&y2h[(((size_t)n * HW) + hh * 64 + wk) * C2 + c];
                float2 f = __half22float2(y);
                v0 = fmaf(f.x, dww[c * 9 + kh * 3 + kw], v0);
                v1 = fmaf(f.y, dww[(c + 1) * 9 + kh * 3 + kw], v1);
            }
        }

    __shared__ float s1[128];
    __shared__ float s2[128];
    s1[t] = v0 + v1; s2[t] = v0 * v0 + v1 * v1;
    __syncthreads();
    if (t < 64) { s1[t] += s1[t + 64]; s2[t] += s2[t + 64]; }
    __syncthreads();
    if (t < 32) {
        float a1 = s1[t] + s1[t + 32];
        float a2 = s2[t] + s2[t + 32];
#pragma unroll
        for (int o = 16; o > 0; o >>= 1) {
            a1 += __shfl_down_sync(0xffffffffu, a1, o);
            a2 += __shfl_down_sync(0xffffffffu, a2, o);
        }
        if (t == 0) { s1[0] = a1; s2[0] = a2; }
    }
    __syncthreads();
    float mean = s1[0] * (1.0f / 256.0f);
    float var  = s2[0] * (1.0f / 256.0f) - mean * mean;
    float rstd = rsqrtf(var + LN_EPS);

    float t0 = fmaf((v0 - mean) * rstd, lg[c],     lb[c]);
    float t1 = fmaf((v1 - mean) * rstd, lg[c + 1], lb[c + 1]);
    float g0 = 0.5f * t0 * (1.0f + erff(t0 * 0.70710678118654752f));
    float g1 = 0.5f * t1 * (1.0f + erff(t1 * 0.70710678118654752f));

    *(uint32_t*)&x1hi[(size_t)pix * C2 + c] = pack_h2(g0, g1);
}

// ---------------------------------------------------------------------------
// DCNv3 core (mask softmax in-kernel), fp16 xproj, half2 math.
// ---------------------------------------------------------------------------
__global__ __launch_bounds__(128) void dcnv3_k(
    const hlf* __restrict__ xproj, const float* __restrict__ om,
    hlf* __restrict__ chi)
{
    const int pix = blockIdx.x;
    const int n = pix >> 12, hw = pix & 4095, h = hw >> 6, w = hw & 63;
    const int t = threadIdx.x;
    const int c = t * 2;

    __shared__ float o[32];
    if (t < 27) o[t] = om[(size_t)pix * 27 + t];
    __syncthreads();
    if (t == 0) {
        float mx = -1e30f;
#pragma unroll
        for (int q = 0; q < 9; q++) mx = fmaxf(mx, o[18 + q]);
        float e[9], sum = 0.0f;
#pragma unroll
        for (int q = 0; q < 9; q++) { e[q] = expf(o[18 + q] - mx); sum += e[q]; }
        float inv = 1.0f / sum;
#pragma unroll
        for (int q = 0; q < 9; q++) o[18 + q] = e[q] * inv;
    }
    __syncthreads();

    const hlf* base = xproj + (size_t)n * HW * C2 + c;
    float a0 = 0.0f, a1 = 0.0f;

#pragma unroll
    for (int p = 0; p < PP; p++) {
        float px = (float)(w + (p / 3)) + o[2 * p];
        float py = (float)(h + (p % 3)) + o[2 * p + 1];
        float x0f = floorf(px), y0f = floorf(py);
        float fx = px - x0f, fy = py - y0f;
        int x0 = (int)x0f, y0 = (int)y0f;
        float mk = o[18 + p];
        float s0 = 0.0f, s1 = 0.0f;
#pragma unroll
        for (int dy = 0; dy < 2; dy++)
#pragma unroll
            for (int dx = 0; dx < 2; dx++) {
                int xi = x0 + dx, yi = y0 + dy;
                if (xi >= 1 && xi <= 64 && yi >= 1 && yi <= 64) {
                    float wgt = (dx ? fx : 1.0f - fx) * (dy ? fy : 1.0f - fy);
                    __half2 v = *(const __half2*)&base[((size_t)(yi - 1) * 64 + (xi - 1)) * C2];
                    float2 f = __half22float2(v);
                    s0 = fmaf(wgt, f.x, s0);
                    s1 = fmaf(wgt, f.y, s1);
                }
            }
        a0 = fmaf(mk, s0, a0);
        a1 = fmaf(mk, s1, a1);
    }
    *(uint32_t*)&chi[(size_t)pix * C2 + c] = pack_h2(a0, a1);
}

// ---------------------------------------------------------------------------
// NHWC->NCHW + BN2 + SiLU + residual (coalesced both ways)
// ---------------------------------------------------------------------------
__global__ __launch_bounds__(256) void bn2_res_transpose_k(
    const float* __restrict__ o, const float* __restrict__ xres,
    const float* __restrict__ g, const float* __restrict__ b,
    float* __restrict__ out)
{
    __shared__ float t[32][33];
    const int n = blockIdx.z, hw0 = blockIdx.x * 32, c0 = blockIdx.y * 32;
    const int tx = threadIdx.x & 31, ty = threadIdx.x >> 5;
#pragma unroll
    for (int i = ty; i < 32; i += 8)
        t[i][tx] = o[((size_t)n * HW + hw0 + i) * C2 + c0 + tx];
    __syncthreads();
#pragma unroll
    for (int i = ty; i < 32; i += 8) {
        int c = c0 + i, hw = hw0 + tx;
        float v = t[tx][i];
        float s = g[c] * rsqrtf(1.0f + BN_EPS);
        v = silu(fmaf(v, s, b[c]));
        size_t idx = ((size_t)n * C2 + c) * HW + hw;
        out[idx] = xres[idx] + v;
    }
}

// ---------------------------------------------------------------------------
// Launch
// ---------------------------------------------------------------------------
extern "C" void kernel_launch(void* const* d_in, const int* in_sizes, int n_in,
                              void* d_out, int out_size) {
    const float* x     = (const float*)d_in[0];
    const float* cv1_w = (const float*)d_in[1];
    const float* cv1_g = (const float*)d_in[2];
    const float* cv1_b = (const float*)d_in[3];
    const float* pw_w  = (const float*)d_in[4];
    const float* pw_g  = (const float*)d_in[5];
    const float* pw_b  = (const float*)d_in[6];
    const float* dw_w  = (const float*)d_in[7];
    const float* dw_b  = (const float*)d_in[8];
    const float* ln_g  = (const float*)d_in[9];
    const float* ln_b  = (const float*)d_in[10];
    const float* off_w = (const float*)d_in[11];
    const float* off_b = (const float*)d_in[12];
    const float* msk_w = (const float*)d_in[13];
    const float* msk_b = (const float*)d_in[14];
    const float* inp_w = (const float*)d_in[15];
    const float* inp_b = (const float*)d_in[16];
    const float* out_w = (const float*)d_in[17];
    const float* out_b = (const float*)d_in[18];
    const float* bn2_g = (const float*)d_in[19];
    const float* bn2_b = (const float*)d_in[20];

    float* sc = nullptr;
    cudaGetSymbolAddress((void**)&sc, g_scratch);
    hlf* xhi  = (hlf*)(sc + OFF_XHI);
    hlf* y1hi = (hlf*)(sc + OFF_Y1HI);
    hlf* y2hi = (hlf*)(sc + OFF_Y2HI);
    hlf* x1hi = (hlf*)(sc + OFF_X1HI);
    hlf* xprojh = (hlf*)(sc + OFF_XPROJ);
    float* om    = sc + OFF_OM;
    hlf* chi  = (hlf*)(sc + OFF_CHI);
    float* onh = sc + OFF_ONH;
    hlf* wt9h = (hlf*)(sc + OFF_WT9H);
    hlf* pwh  = (hlf*)(sc + OFF_PWH);
    hlf* inh  = (hlf*)(sc + OFF_INH);
    hlf* ouh  = (hlf*)(sc + OFF_OUH);
    hlf* hwh  = (hlf*)(sc + OFF_HWH);
    float* hb = sc + OFF_HB;
    float* outp = (float*)d_out;

    cudaFuncSetAttribute(mma_conv_k, cudaFuncAttributeMaxDynamicSharedMemorySize, CONV_SMEM);
    cudaFuncSetAttribute(mma_gemm_k<128, 0>, cudaFuncAttributeMaxDynamicSharedMemorySize, GEMM_SMEM1);
    cudaFuncSetAttribute(mma_gemm_k<256, 2>, cudaFuncAttributeMaxDynamicSharedMemorySize, GEMM_SMEM1);
    cudaFuncSetAttribute(mma_gemm_k<256, 1>, cudaFuncAttributeMaxDynamicSharedMemorySize, GEMM_SMEM1);
    cudaFuncSetAttribute(mma_head_k, cudaFuncAttributeMaxDynamicSharedMemorySize, HEAD_SMEM);

    // 0) preprocessing
    prep_x_k<<<dim3(HW / 32, C1 / 32, NB), 256>>>(x, xhi);
    int prep_tot = 9 * CM * C1 + C2 * CM + 2 * C2 * C2 + 32 * C2 + 32;
    prep_w_k<<<(prep_tot + 255) / 256, 256>>>(
        cv1_w, pw_w, inp_w, out_w, off_w, msk_w, off_b, msk_b,
        wt9h, pwh, inh, ouh, hwh, hb);

    // 1) cv1 (1-term fp16, 4-stage) -> y1hi
    mma_conv_k<<<NPIX / 64, 256, CONV_SMEM>>>(
        xhi, wt9h, cv1_g, cv1_b, y1hi);

    // 2) pw (1-term, 4-stage, N-loop) -> y2hi
    mma_gemm_k<128, 0><<<NPIX / 64, 256, GEMM_SMEM1>>>(
        y1hi, pwh, pw_g, pw_b, nullptr, y2hi);

    // 3) dw (half2) + LN + GELU -> x1hi
    dw_ln_gelu_k<<<NPIX, 128>>>(y2hi, dw_w, dw_b, ln_g, ln_b, x1hi);

    // 4) offset/mask heads (1-term) -> om (logits)
    mma_head_k<<<NPIX / 128, 256, HEAD_SMEM>>>(x1hi, hwh, hb, om);

    // 5) input_proj (1-term, 4-stage, N-loop) -> xproj fp16
    mma_gemm_k<256, 2><<<NPIX / 64, 256, GEMM_SMEM1>>>(
        y2hi, inh, inp_b, nullptr, nullptr, xprojh);

    // 6) DCNv3 core (half2, softmax inside) -> chi fp16
    dcnv3_k<<<NPIX, 128>>>(xprojh, om, chi);

    // 7) output_proj (1-term, 4-stage, N-loop) + bias -> onh f32 NHWC
    mma_gemm_k<256, 1><<<NPIX / 64, 256, GEMM_SMEM1>>>(
        chi, ouh, out_b, nullptr, onh, nullptr);

    // 8) BN2 + SiLU + residual + transpose -> d_out NCHW
    bn2_res_transpose_k<<<dim3(HW / 32, C2 / 32, NB), 256>>>(onh, x, bn2_g, bn2_b, outp);
}

// round 17
// speedup vs baseline: 1.0542x; 1.0542x over previous
#include <cuda_runtime.h>
#include <cuda_fp16.h>
#include <math.h>
#include <stdint.h>

// ---------------------------------------------------------------------------
// Problem constants
// ---------------------------------------------------------------------------
#define NB   4
#define C1   256
#define CM   128
#define C2   256
#define HW   4096
#define NPIX (NB*HW)
#define PP   9
#define NTILES 4096            // NB * 32 * 32 Winograd tiles
#define BN_EPS 1e-5f
#define LN_EPS 1e-6f

typedef __half hlf;

// ---------------------------------------------------------------------------
// Scratch (offsets in floats)
// ---------------------------------------------------------------------------
#define OFF_XHI   0                            // NPIX*C1 fp16
#define OFF_Y1HI  (OFF_XHI  + NPIX*C1/2)       // NPIX*CM fp16
#define OFF_Y2HI  (OFF_Y1HI + NPIX*CM/2)       // NPIX*C2 fp16
#define OFF_X1HI  (OFF_Y2HI + NPIX*C2/2)       // NPIX*C2 fp16
#define OFF_XPROJ (OFF_X1HI + NPIX*C2/2)       // fp16
#define OFF_OM    (OFF_XPROJ+ NPIX*C2/2)
#define OFF_CHI   (OFF_OM   + NPIX*27)         // fp16
#define OFF_ONH   (OFF_CHI  + NPIX*C2/2)       // f32 NHWC out_proj result
#define OFF_VBUF  (OFF_ONH  + NPIX*C2)         // 16*NTILES*256 fp16
#define OFF_MBUF  (OFF_VBUF + 16*NTILES*256/2) // 16*NTILES*128 fp16
#define OFF_UW    (OFF_MBUF + 16*NTILES*128/2) // 16*128*256 fp16
#define OFF_PWH   (OFF_UW   + 16*128*256/2)
#define OFF_INH   (OFF_PWH  + C2*CM/2)
#define OFF_OUH   (OFF_INH  + C2*C2/2)
#define OFF_HWH   (OFF_OUH  + C2*C2/2)         // 32*256 fp16 head weights
#define OFF_HB    (OFF_HWH  + 32*C2/2)         // 32 f32 head bias
#define SCRATCH_FLOATS (OFF_HB + 32)

__device__ __align__(16) float g_scratch[SCRATCH_FLOATS];

__device__ __forceinline__ float silu(float v) { return v / (1.0f + expf(-v)); }

__device__ __forceinline__ uint32_t pack_h2(float a, float b) {
    hlf ha = __float2half_rn(a), hb = __float2half_rn(b);
    return ((uint32_t)*(uint16_t*)&hb << 16) | *(uint16_t*)&ha;
}
__device__ __forceinline__ float2 f2add(float2 a, float2 b) { return make_float2(a.x + b.x, a.y + b.y); }
__device__ __forceinline__ float2 f2sub(float2 a, float2 b) { return make_float2(a.x - b.x, a.y - b.y); }

// ---------------------------------------------------------------------------
// mma.sync + ldmatrix + cp.async (portable sm_80 PTX)
// ---------------------------------------------------------------------------
__device__ __forceinline__ void mma16816(float* d, const uint32_t* a, const uint32_t* b) {
    asm volatile("mma.sync.aligned.m16n8k16.row.col.f32.f16.f16.f32 "
        "{%0,%1,%2,%3}, {%4,%5,%6,%7}, {%8,%9}, {%0,%1,%2,%3};"
        : "+f"(d[0]), "+f"(d[1]), "+f"(d[2]), "+f"(d[3])
        : "r"(a[0]), "r"(a[1]), "r"(a[2]), "r"(a[3]), "r"(b[0]), "r"(b[1]));
}
__device__ __forceinline__ void ldm4(uint32_t* r, uint32_t addr) {
    asm volatile("ldmatrix.sync.aligned.m8n8.x4.shared.b16 {%0,%1,%2,%3}, [%4];"
        : "=r"(r[0]), "=r"(r[1]), "=r"(r[2]), "=r"(r[3]) : "r"(addr));
}
__device__ __forceinline__ void cp16(uint32_t dst, const void* src) {
    asm volatile("cp.async.cg.shared.global [%0], [%1], 16;" :: "r"(dst), "l"(src));
}
#define CP_COMMIT() asm volatile("cp.async.commit_group;" ::: "memory")
#define CP_WAIT2()  asm volatile("cp.async.wait_group 2;" ::: "memory")

// SMEM row: 32 fp16 = 16 words, padded to 20 (conflict-free for ldmatrix)
#define TS 20
#define AW  (64 * TS)
#define BW  (128 * TS)
#define GEMM_STW1 (AW + BW)
#define GEMM_SMEM1 (4 * GEMM_STW1 * 4)      // 4-stage ring

// ---------------------------------------------------------------------------
// prep_x: NCHW f32 -> NHWC fp16
// ---------------------------------------------------------------------------
__global__ __launch_bounds__(256) void prep_x_k(
    const float* __restrict__ x, hlf* __restrict__ xhi)
{
    __shared__ float t[32][33];
    const int n = blockIdx.z, hw0 = blockIdx.x * 32, c0 = blockIdx.y * 32;
    const int tx = threadIdx.x & 31, ty = threadIdx.x >> 5;
#pragma unroll
    for (int i = ty; i < 32; i += 8)
        t[i][tx] = x[((size_t)n * C1 + c0 + i) * HW + hw0 + tx];
    __syncthreads();
#pragma unroll
    for (int i = ty; i < 32; i += 8) {
        size_t idx = ((size_t)n * HW + hw0 + i) * C1 + c0 + tx;
        xhi[idx] = __float2half_rn(t[tx][i]);
    }
}

// ---------------------------------------------------------------------------
// prep_w: pw/inp/out/head weights -> fp16
// ---------------------------------------------------------------------------
__global__ __launch_bounds__(256) void prep_w_k(
    const float* __restrict__ pww,
    const float* __restrict__ inpw, const float* __restrict__ outw,
    const float* __restrict__ offw, const float* __restrict__ mskw,
    const float* __restrict__ offb, const float* __restrict__ mskb,
    hlf* __restrict__ pwh,
    hlf* __restrict__ inh,  hlf* __restrict__ ouh,
    hlf* __restrict__ hwh,  float* __restrict__ hb)
{
    int idx = blockIdx.x * 256 + threadIdx.x;
    if (idx < C2 * CM) { pwh[idx] = __float2half_rn(pww[idx]); return; }
    idx -= C2 * CM;
    if (idx < C2 * C2) { inh[idx] = __float2half_rn(inpw[idx]); return; }
    idx -= C2 * C2;
    if (idx < C2 * C2) { ouh[idx] = __float2half_rn(outw[idx]); return; }
    idx -= C2 * C2;
    if (idx < 32 * C2) {
        int j = idx >> 8, k = idx & 255;
        float v = (j < 18) ? offw[j * C2 + k] : ((j < 27) ? mskw[(j - 18) * C2 + k] : 0.0f);
        hwh[idx] = __float2half_rn(v); return;
    }
    idx -= 32 * C2;
    if (idx < 32)
        hb[idx] = (idx < 18) ? offb[idx] : ((idx < 27) ? mskb[idx - 18] : 0.0f);
}

// ---------------------------------------------------------------------------
// wino_w: U[t][co][ci] = (G g G^T)[t], fp16
// ---------------------------------------------------------------------------
__global__ __launch_bounds__(256) void wino_w_k(
    const float* __restrict__ cv1w, hlf* __restrict__ U)
{
    int idx = blockIdx.x * 256 + threadIdx.x;
    if (idx >= CM * C1) return;
    int co = idx >> 8, ci = idx & 255;
    const float* gp = cv1w + (size_t)co * (C1 * 9) + ci * 9;
    float g0[3], g1[3], g2[3];
#pragma unroll
    for (int j = 0; j < 3; j++) { g0[j] = gp[j]; g1[j] = gp[3 + j]; g2[j] = gp[6 + j]; }
    float a[4][3];
#pragma unroll
    for (int j = 0; j < 3; j++) {
        a[0][j] = g0[j];
        a[1][j] = 0.5f * (g0[j] + g1[j] + g2[j]);
        a[2][j] = 0.5f * (g0[j] - g1[j] + g2[j]);
        a[3][j] = g2[j];
    }
#pragma unroll
    for (int r = 0; r < 4; r++) {
        float u0 = a[r][0];
        float u1 = 0.5f * (a[r][0] + a[r][1] + a[r][2]);
        float u2 = 0.5f * (a[r][0] - a[r][1] + a[r][2]);
        float u3 = a[r][2];
        U[((size_t)(r * 4 + 0) * CM + co) * C1 + ci] = __float2half_rn(u0);
        U[((size_t)(r * 4 + 1) * CM + co) * C1 + ci] = __float2half_rn(u1);
        U[((size_t)(r * 4 + 2) * CM + co) * C1 + ci] = __float2half_rn(u2);
        U[((size_t)(r * 4 + 3) * CM + co) * C1 + ci] = __float2half_rn(u3);
    }
}

// ---------------------------------------------------------------------------
// wino_inp: V[t][tile][ci] = (B^T d B)[t], fp16. Block: 2 tiles x 128 ci-pairs.
// ---------------------------------------------------------------------------
__global__ __launch_bounds__(256) void wino_inp_k(
    const hlf* __restrict__ xhi, hlf* __restrict__ V)
{
    const int tid = threadIdx.x;
    const int sub = tid >> 7, cp = tid & 127, c = cp * 2;
    const int tile = blockIdx.x * 2 + sub;
    const int n = tile >> 10, rr = tile & 1023, ty = rr >> 5, tx = rr & 31;

    float2 d[4][4];
#pragma unroll
    for (int i = 0; i < 4; i++)
#pragma unroll
        for (int j = 0; j < 4; j++) {
            int ih = 2 * ty - 1 + i, iw = 2 * tx - 1 + j;
            if ((unsigned)ih < 64u && (unsigned)iw < 64u) {
                __half2 v = *(const __half2*)&xhi[((size_t)n * HW + ih * 64 + iw) * C1 + c];
                d[i][j] = __half22float2(v);
            } else d[i][j] = make_float2(0.0f, 0.0f);
        }

    float2 t[4][4];
#pragma unroll
    for (int j = 0; j < 4; j++) {
        t[0][j] = f2sub(d[0][j], d[2][j]);
        t[1][j] = f2add(d[1][j], d[2][j]);
        t[2][j] = f2sub(d[2][j], d[1][j]);
        t[3][j] = f2sub(d[1][j], d[3][j]);
    }
#pragma unroll
    for (int i = 0; i < 4; i++) {
        float2 v0 = f2sub(t[i][0], t[i][2]);
        float2 v1 = f2add(t[i][1], t[i][2]);
        float2 v2 = f2sub(t[i][2], t[i][1]);
        float2 v3 = f2sub(t[i][1], t[i][3]);
        *(uint32_t*)&V[((size_t)(i * 4 + 0) * NTILES + tile) * C1 + c] = pack_h2(v0.x, v0.y);
        *(uint32_t*)&V[((size_t)(i * 4 + 1) * NTILES + tile) * C1 + c] = pack_h2(v1.x, v1.y);
        *(uint32_t*)&V[((size_t)(i * 4 + 2) * NTILES + tile) * C1 + c] = pack_h2(v2.x, v2.y);
        *(uint32_t*)&V[((size_t)(i * 4 + 3) * NTILES + tile) * C1 + c] = pack_h2(v3.x, v3.y);
    }
}

// ---------------------------------------------------------------------------
// Inner MMA via ldmatrix. A tile 64x32 (fp16), B tile 128x32.
// ---------------------------------------------------------------------------
__device__ __forceinline__ void mma_step1(
    uint32_t aHi, uint32_t bHi, int wm, int wn, int lane, float acc[2][4][4])
{
    const int arow = (lane & 7) + ((lane >> 3) & 1) * 8;
    const int akt  = (lane >> 4) & 1;
    const int brow = (lane & 7) + ((lane >> 4) & 1) * 8;
    const int bkt  = (lane >> 3) & 1;
#pragma unroll
    for (int ks = 0; ks < 2; ks++) {
        uint32_t ahi[2][4], bhi[2][4];
#pragma unroll
        for (int mt = 0; mt < 2; mt++) {
            uint32_t off = (uint32_t)(((wm * 32 + mt * 16 + arow) * TS + ks * 8 + akt * 4) * 4);
            ldm4(ahi[mt], aHi + off);
        }
#pragma unroll
        for (int np = 0; np < 2; np++) {
            uint32_t off = (uint32_t)(((wn * 32 + np * 16 + brow) * TS + ks * 8 + bkt * 4) * 4);
            ldm4(bhi[np], bHi + off);
        }
#pragma unroll
        for (int mt = 0; mt < 2; mt++)
#pragma unroll
            for (int nt = 0; nt < 4; nt++)
                mma16816(acc[mt][nt], ahi[mt], &bhi[nt >> 1][(nt & 1) * 2]);
    }
}

// ---------------------------------------------------------------------------
// wino_gemm: M_t[tiles,128] = V_t[tiles,256] @ U_t[128,256]^T, fp16 out.
// grid (NTILES/64, 16); 4-stage single-sync ring.
// ---------------------------------------------------------------------------
__global__ __launch_bounds__(256, 2) void wino_gemm_k(
    const hlf* __restrict__ Vb, const hlf* __restrict__ Ub, hlf* __restrict__ Mb)
{
    extern __shared__ __align__(16) uint32_t dsm[];
    const uint32_t sbase = (uint32_t)__cvta_generic_to_shared(dsm);
    constexpr int STW = AW + BW;

    const int tid = threadIdx.x, wid = tid >> 5, lane = tid & 31;
    const int wm = wid >> 2, wn = wid & 3, qr = lane >> 2, qc = lane & 3;
    const int tp = blockIdx.y;
    const hlf* A = Vb + (size_t)tp * NTILES * C1;
    const hlf* B = Ub + (size_t)tp * CM * C1;
    hlf* Mo = Mb + (size_t)tp * NTILES * CM;
    const int pix0 = blockIdx.x * 64;
    const int r0 = tid >> 2, ch0 = tid & 3;

    constexpr int TOT = 8;   // K=256 / 32

    float acc[2][4][4];
#pragma unroll
    for (int mt = 0; mt < 2; mt++)
#pragma unroll
        for (int nt = 0; nt < 4; nt++)
#pragma unroll
            for (int q = 0; q < 4; q++) acc[mt][nt][q] = 0.0f;

    auto stage = [&](int it) {
        const int kc = it;
        const uint32_t sb = sbase + (uint32_t)(it & 3) * (STW * 4);
        {
            size_t a4 = (size_t)(pix0 + r0) * 32 + kc * 4 + ch0;
            uint32_t rowoff = (uint32_t)(r0 * TS + ch0 * 4) * 4;
            cp16(sb + rowoff, (const char*)A + a4 * 16);
        }
#pragma unroll
        for (int i = 0; i < 2; i++) {
            int r = r0 + i * 64;
            size_t b4 = (size_t)r * 32 + kc * 4 + ch0;
            uint32_t rowoff = (uint32_t)(r * TS + ch0 * 4) * 4;
            cp16(sb + AW * 4 + rowoff, (const char*)B + b4 * 16);
        }
    };

    stage(0); CP_COMMIT();
    stage(1); CP_COMMIT();
    for (int it = 0; it < TOT; it++) {
        if (it + 2 < TOT) stage(it + 2);
        CP_COMMIT();
        CP_WAIT2();
        __syncthreads();
        uint32_t sb = sbase + (uint32_t)(it & 3) * (STW * 4);
        mma_step1(sb, sb + AW * 4, wm, wn, lane, acc);
    }

#pragma unroll
    for (int nt = 0; nt < 4; nt++) {
        int c = wn * 32 + nt * 8 + qc * 2;
#pragma unroll
        for (int mt = 0; mt < 2; mt++) {
            int row = wm * 32 + mt * 16 + qr;
#pragma unroll
            for (int half = 0; half < 2; half++) {
                int pix = pix0 + row + half * 8;
                *(uint32_t*)&Mo[(size_t)pix * CM + c] =
                    pack_h2(acc[mt][nt][half * 2 + 0], acc[mt][nt][half * 2 + 1]);
            }
        }
    }
}

// ---------------------------------------------------------------------------
// wino_out: y1 = BN(SiLU(A^T M A)). Block: 4 tiles x 64 co-pairs.
// ---------------------------------------------------------------------------
__global__ __launch_bounds__(256) void wino_out_k(
    const hlf* __restrict__ Mb, const float* __restrict__ g,
    const float* __restrict__ b, hlf* __restrict__ y1hi)
{
    const int tid = threadIdx.x;
    const int sub = tid >> 6, cp = tid & 63, c = cp * 2;
    const int tile = blockIdx.x * 4 + sub;
    const int n = tile >> 10, rr = tile & 1023, ty = rr >> 5, tx = rr & 31;

    float2 m[16];
#pragma unroll
    for (int t = 0; t < 16; t++) {
        __half2 v = *(const __half2*)&Mb[((size_t)t * NTILES + tile) * CM + c];
        m[t] = __half22float2(v);
    }
    float2 z[2][4];
#pragma unroll
    for (int j = 0; j < 4; j++) {
        z[0][j] = f2add(f2add(m[j], m[4 + j]), m[8 + j]);
        z[1][j] = f2sub(f2sub(m[4 + j], m[8 + j]), m[12 + j]);
    }
    float2 Y[2][2];
#pragma unroll
    for (int i = 0; i < 2; i++) {
        Y[i][0] = f2add(f2add(z[i][0], z[i][1]), z[i][2]);
        Y[i][1] = f2sub(f2sub(z[i][1], z[i][2]), z[i][3]);
    }

    const float s0 = g[c] * rsqrtf(1.0f + BN_EPS),     b0 = b[c];
    const float s1 = g[c + 1] * rsqrtf(1.0f + BN_EPS), b1 = b[c + 1];
#pragma unroll
    for (int i = 0; i < 2; i++)
#pragma unroll
        for (int jj = 0; jj < 2; jj++) {
            int pix = n * HW + (2 * ty + i) * 64 + (2 * tx + jj);
            float v0 = silu(fmaf(Y[i][jj].x, s0, b0));
            float v1 = silu(fmaf(Y[i][jj].y, s1, b1));
            *(uint32_t*)&y1hi[(size_t)pix * CM + c] = pack_h2(v0, v1);
        }
}

// ---------------------------------------------------------------------------
// mma_gemm_nl: pw GEMM, in-block N-half loop (K=128). MODE0: BN+SiLU -> fp16.
// ---------------------------------------------------------------------------
__global__ __launch_bounds__(256, 2) void mma_gemm_nl_k(
    const hlf* __restrict__ Ahi, const hlf* __restrict__ Whi,
    const float* __restrict__ p0, const float* __restrict__ p1,
    hlf* __restrict__ outhi)
{
    extern __shared__ __align__(16) uint32_t dsm[];
    const uint32_t sbase = (uint32_t)__cvta_generic_to_shared(dsm);
    constexpr int STW = AW + BW;
    constexpr int K = 128;
    constexpr int NIT = K / 32;
    constexpr int TOT = 2 * NIT;

    const int tid = threadIdx.x, wid = tid >> 5, lane = tid & 31;
    const int wm = wid >> 2, wn = wid & 3, qr = lane >> 2, qc = lane & 3;
    const int pix0 = blockIdx.x * 64;
    const int r0 = tid >> 2, ch0 = tid & 3;

    float acc[2][4][4];
#pragma unroll
    for (int mt = 0; mt < 2; mt++)
#pragma unroll
        for (int nt = 0; nt < 4; nt++)
#pragma unroll
            for (int q = 0; q < 4; q++) acc[mt][nt][q] = 0.0f;

    auto stage = [&](int it) {
        const int nh = it / NIT, kc = it % NIT;
        const uint32_t sb = sbase + (uint32_t)(it & 3) * (STW * 4);
        {
            size_t a4 = (size_t)(pix0 + r0) * (K / 8) + kc * 4 + ch0;
            uint32_t rowoff = (uint32_t)(r0 * TS + ch0 * 4) * 4;
            cp16(sb + rowoff, (const char*)Ahi + a4 * 16);
        }
#pragma unroll
        for (int i = 0; i < 2; i++) {
            int r = r0 + i * 64;
            size_t b4 = (size_t)(nh * 128 + r) * (K / 8) + kc * 4 + ch0;
            uint32_t rowoff = (uint32_t)(r * TS + ch0 * 4) * 4;
            cp16(sb + AW * 4 + rowoff, (const char*)Whi + b4 * 16);
        }
    };

    stage(0); CP_COMMIT();
    stage(1); CP_COMMIT();
    for (int it = 0; it < TOT; it++) {
        if (it + 2 < TOT) stage(it + 2);
        CP_COMMIT();
        CP_WAIT2();
        __syncthreads();
        uint32_t sb = sbase + (uint32_t)(it & 3) * (STW * 4);
        mma_step1(sb, sb + AW * 4, wm, wn, lane, acc);

        if ((it + 1) % NIT == 0) {
            const int nh = it / NIT;
#pragma unroll
            for (int nt = 0; nt < 4; nt++) {
                int c = nh * 128 + wn * 32 + nt * 8 + qc * 2;
                float s0 = p0[c] * rsqrtf(1.0f + BN_EPS),     b0 = p1[c];
                float s1 = p0[c + 1] * rsqrtf(1.0f + BN_EPS), b1 = p1[c + 1];
#pragma unroll
                for (int mt = 0; mt < 2; mt++) {
                    int row = wm * 32 + mt * 16 + qr;
#pragma unroll
                    for (int half = 0; half < 2; half++) {
                        int pix = pix0 + row + half * 8;
                        float v0 = silu(fmaf(acc[mt][nt][half * 2 + 0], s0, b0));
                        float v1 = silu(fmaf(acc[mt][nt][half * 2 + 1], s1, b1));
                        *(uint32_t*)&outhi[(size_t)pix * C2 + c] = pack_h2(v0, v1);
                    }
                }
            }
#pragma unroll
            for (int mt = 0; mt < 2; mt++)
#pragma unroll
                for (int nt = 0; nt < 4; nt++)
#pragma unroll
                    for (int q = 0; q < 4; q++) acc[mt][nt][q] = 0.0f;
        }
    }
}

// ---------------------------------------------------------------------------
// mma_gemm: K=256 GEMMs, grid.y = N-half. MODE 1: +bias -> f32. MODE 2: -> fp16.
// ---------------------------------------------------------------------------
template<int MODE>
__global__ __launch_bounds__(256, 2) void mma_gemm_k(
    const hlf* __restrict__ Ahi, const hlf* __restrict__ Whi,
    const float* __restrict__ p0,
    float* __restrict__ outf, hlf* __restrict__ outhi)
{
    extern __shared__ __align__(16) uint32_t dsm[];
    const uint32_t sbase = (uint32_t)__cvta_generic_to_shared(dsm);
    constexpr int STW = AW + BW;
    constexpr int K = 256;
    constexpr int TOT = K / 32;

    const int tid = threadIdx.x, wid = tid >> 5, lane = tid & 31;
    const int wm = wid >> 2, wn = wid & 3, qr = lane >> 2, qc = lane & 3;
    const int pix0 = blockIdx.x * 64;
    const int nh = blockIdx.y;
    const int r0 = tid >> 2, ch0 = tid & 3;

    float acc[2][4][4];
#pragma unroll
    for (int mt = 0; mt < 2; mt++)
#pragma unroll
        for (int nt = 0; nt < 4; nt++)
#pragma unroll
            for (int q = 0; q < 4; q++) acc[mt][nt][q] = 0.0f;

    auto stage = [&](int it) {
        const int kc = it;
        const uint32_t sb = sbase + (uint32_t)(it & 3) * (STW * 4);
        {
            size_t a4 = (size_t)(pix0 + r0) * (K / 8) + kc * 4 + ch0;
            uint32_t rowoff = (uint32_t)(r0 * TS + ch0 * 4) * 4;
            cp16(sb + rowoff, (const char*)Ahi + a4 * 16);
        }
#pragma unroll
        for (int i = 0; i < 2; i++) {
            int r = r0 + i * 64;
            size_t b4 = (size_t)(nh * 128 + r) * (K / 8) + kc * 4 + ch0;
            uint32_t rowoff = (uint32_t)(r * TS + ch0 * 4) * 4;
            cp16(sb + AW * 4 + rowoff, (const char*)Whi + b4 * 16);
        }
    };

    stage(0); CP_COMMIT();
    stage(1); CP_COMMIT();
    for (int it = 0; it < TOT; it++) {
        if (it + 2 < TOT) stage(it + 2);
        CP_COMMIT();
        CP_WAIT2();
        __syncthreads();
        uint32_t sb = sbase + (uint32_t)(it & 3) * (STW * 4);
        mma_step1(sb, sb + AW * 4, wm, wn, lane, acc);
    }

#pragma unroll
    for (int nt = 0; nt < 4; nt++) {
        int c = nh * 128 + wn * 32 + nt * 8 + qc * 2;
        float b0 = p0[c], b1 = p0[c + 1];
#pragma unroll
        for (int mt = 0; mt < 2; mt++) {
            int row = wm * 32 + mt * 16 + qr;
#pragma unroll
            for (int half = 0; half < 2; half++) {
                int pix = pix0 + row + half * 8;
                float v0 = acc[mt][nt][half * 2 + 0] + b0;
                float v1 = acc[mt][nt][half * 2 + 1] + b1;
                if (MODE == 1)
                    *(float2*)&outf[(size_t)pix * C2 + c] = make_float2(v0, v1);
                else
                    *(uint32_t*)&outhi[(size_t)pix * C2 + c] = pack_h2(v0, v1);
            }
        }
    }
}

// ---------------------------------------------------------------------------
// mma_head: om[M,27] = x1hi[M,256] @ HW16[32,256]^T + hb (1-term fp16).
// ---------------------------------------------------------------------------
#define BS2 132
#define HEAD_SMEM ((128*TS + 32*BS2) * 4)
__global__ __launch_bounds__(256) void mma_head_k(
    const hlf* __restrict__ x1hi, const hlf* __restrict__ hwh,
    const float* __restrict__ hb, float* __restrict__ om)
{
    extern __shared__ __align__(16) uint32_t dsm[];
    const uint32_t sbase = (uint32_t)__cvta_generic_to_shared(dsm);
    const uint32_t AHI = 0, BHI = 128 * TS;

    const int tid = threadIdx.x, wid = tid >> 5, lane = tid & 31;
    const int pix0 = blockIdx.x * 128;

    for (int i = tid; i < 1024; i += 256) {
        int row = i >> 5, ch = i & 31;
        *(uint4*)&dsm[BHI + row * BS2 + ch * 4] = ((const uint4*)hwh)[row * 32 + ch];
    }

    float acc[4][4];
#pragma unroll
    for (int nt = 0; nt < 4; nt++)
#pragma unroll
        for (int q = 0; q < 4; q++) acc[nt][q] = 0.0f;

    const int arow = (lane & 7) + ((lane >> 3) & 1) * 8;
    const int akt  = (lane >> 4) & 1;
    const int brow = (lane & 7) + ((lane >> 4) & 1) * 8;
    const int bkt  = (lane >> 3) & 1;

    for (int kc = 0; kc < 8; kc++) {
        __syncthreads();
        for (int i = tid; i < 512; i += 256) {
            int row = i >> 2, ch = i & 3;
            const uint4 v = ((const uint4*)x1hi)[(size_t)(pix0 + row) * 32 + kc * 4 + ch];
            *(uint4*)&dsm[AHI + row * TS + ch * 4] = v;
        }
        __syncthreads();
#pragma unroll
        for (int ks = 0; ks < 2; ks++) {
            uint32_t ahi[4], bhi[2][4];
            uint32_t aoff = (uint32_t)(((wid * 16 + arow) * TS + ks * 8 + akt * 4) * 4);
            ldm4(ahi, sbase + AHI * 4 + aoff);
#pragma unroll
            for (int np = 0; np < 2; np++) {
                uint32_t boff = (uint32_t)(((np * 16 + brow) * BS2 + kc * 16 + ks * 8 + bkt * 4) * 4);
                ldm4(bhi[np], sbase + BHI * 4 + boff);
            }
#pragma unroll
            for (int nt = 0; nt < 4; nt++)
                mma16816(acc[nt], ahi, &bhi[nt >> 1][(nt & 1) * 2]);
        }
    }

#pragma unroll
    for (int nt = 0; nt < 4; nt++) {
        int c = nt * 8 + (lane & 3) * 2;
        int r0p = pix0 + wid * 16 + (lane >> 2);
#pragma unroll
        for (int half = 0; half < 2; half++) {
            int pix = r0p + half * 8;
            float v0 = acc[nt][half * 2 + 0] + hb[c];
            float v1 = acc[nt][half * 2 + 1] + hb[c + 1];
            if (c < 27)     om[(size_t)pix * 27 + c]     = v0;
            if (c + 1 < 27) om[(size_t)pix * 27 + c + 1] = v1;
        }
    }
}

// ---------------------------------------------------------------------------
// Fused: depthwise 3x3 (fp16 y2hi, half2) + LN + GELU -> x1hi
// ---------------------------------------------------------------------------
__global__ __launch_bounds__(128) void dw_ln_gelu_k(
    const hlf* __restrict__ y2h,
    const float* __restrict__ dww, const float* __restrict__ dwb,
    const float* __restrict__ lg,  const float* __restrict__ lb,
    hlf* __restrict__ x1hi)
{
    const int pix = blockIdx.x;
    const int n = pix >> 12, hw = pix & 4095, h = hw >> 6, w = hw & 63;
    const int t = threadIdx.x;
    const int c = t * 2;

    float v0 = dwb[c], v1 = dwb[c + 1];
#pragma unroll
    for (int kh = 0; kh < 3; kh++)
#pragma unroll
        for (int kw = 0; kw < 3; kw++) {
            int hh = h + kh - 1, wk = w + kw - 1;
            if ((unsigned)hh < 64u && (unsigned)wk < 64u) {
                __half2 y = *(const __half2*)&y2h[(((size_t)n * HW) + hh * 64 + wk) * C2 + c];
                float2 f = __half22float2(y);
                v0 = fmaf(f.x, dww[c * 9 + kh * 3 + kw], v0);
                v1 = fmaf(f.y, dww[(c + 1) * 9 + kh * 3 + kw], v1);
            }
        }

    __shared__ float s1[128];
    __shared__ float s2[128];
    s1[t] = v0 + v1; s2[t] = v0 * v0 + v1 * v1;
    __syncthreads();
    if (t < 64) { s1[t] += s1[t + 64]; s2[t] += s2[t + 64]; }
    __syncthreads();
    if (t < 32) {
        float a1 = s1[t] + s1[t + 32];
        float a2 = s2[t] + s2[t + 32];
#pragma unroll
        for (int o = 16; o > 0; o >>= 1) {
            a1 += __shfl_down_sync(0xffffffffu, a1, o);
            a2 += __shfl_down_sync(0xffffffffu, a2, o);
        }
        if (t == 0) { s1[0] = a1; s2[0] = a2; }
    }
    __syncthreads();
    float mean = s1[0] * (1.0f / 256.0f);
    float var  = s2[0] * (1.0f / 256.0f) - mean * mean;
    float rstd = rsqrtf(var + LN_EPS);

    float t0 = fmaf((v0 - mean) * rstd, lg[c],     lb[c]);
    float t1 = fmaf((v1 - mean) * rstd, lg[c + 1], lb[c + 1]);
    float g0 = 0.5f * t0 * (1.0f + erff(t0 * 0.70710678118654752f));
    float g1 = 0.5f * t1 * (1.0f + erff(t1 * 0.70710678118654752f));

    *(uint32_t*)&x1hi[(size_t)pix * C2 + c] = pack_h2(g0, g1);
}

// ---------------------------------------------------------------------------
// DCNv3 core (mask softmax in-kernel), fp16 xproj, half2 math.
// ---------------------------------------------------------------------------
__global__ __launch_bounds__(128) void dcnv3_k(
    const hlf* __restrict__ xproj, const float* __restrict__ om,
    hlf* __restrict__ chi)
{
    const int pix = blockIdx.x;
    const int n = pix >> 12, hw = pix & 4095, h = hw >> 6, w = hw & 63;
    const int t = threadIdx.x;
    const int c = t * 2;

    __shared__ float o[32];
    if (t < 27) o[t] = om[(size_t)pix * 27 + t];
    __syncthreads();
    if (t == 0) {
        float mx = -1e30f;
#pragma unroll
        for (int q = 0; q < 9; q++) mx = fmaxf(mx, o[18 + q]);
        float e[9], sum = 0.0f;
#pragma unroll
        for (int q = 0; q < 9; q++) { e[q] = expf(o[18 + q] - mx); sum += e[q]; }
        float inv = 1.0f / sum;
#pragma unroll
        for (int q = 0; q < 9; q++) o[18 + q] = e[q] * inv;
    }
    __syncthreads();

    const hlf* base = xproj + (size_t)n * HW * C2 + c;
    float a0 = 0.0f, a1 = 0.0f;

#pragma unroll
    for (int p = 0; p < PP; p++) {
        float px = (float)(w + (p / 3)) + o[2 * p];
        float py = (float)(h + (p % 3)) + o[2 * p + 1];
        float x0f = floorf(px), y0f = floorf(py);
        float fx = px - x0f, fy = py - y0f;
        int x0 = (int)x0f, y0 = (int)y0f;
        float mk = o[18 + p];
        float s0 = 0.0f, s1 = 0.0f;
#pragma unroll
        for (int dy = 0; dy < 2; dy++)
#pragma unroll
            for (int dx = 0; dx < 2; dx++) {
                int xi = x0 + dx, yi = y0 + dy;
                if (xi >= 1 && xi <= 64 && yi >= 1 && yi <= 64) {
                    float wgt = (dx ? fx : 1.0f - fx) * (dy ? fy : 1.0f - fy);
                    __half2 v = *(const __half2*)&base[((size_t)(yi - 1) * 64 + (xi - 1)) * C2];
                    float2 f = __half22float2(v);
                    s0 = fmaf(wgt, f.x, s0);
                    s1 = fmaf(wgt, f.y, s1);
                }
            }
        a0 = fmaf(mk, s0, a0);
        a1 = fmaf(mk, s1, a1);
    }
    *(uint32_t*)&chi[(size_t)pix * C2 + c] = pack_h2(a0, a1);
}

// ---------------------------------------------------------------------------
// NHWC->NCHW + BN2 + SiLU + residual (coalesced both ways)
// ---------------------------------------------------------------------------
__global__ __launch_bounds__(256) void bn2_res_transpose_k(
    const float* __restrict__ o, const float* __restrict__ xres,
    const float* __restrict__ g, const float* __restrict__ b,
    float* __restrict__ out)
{
    __shared__ float t[32][33];
    const int n = blockIdx.z, hw0 = blockIdx.x * 32, c0 = blockIdx.y * 32;
    const int tx = threadIdx.x & 31, ty = threadIdx.x >> 5;
#pragma unroll
    for (int i = ty; i < 32; i += 8)
        t[i][tx] = o[((size_t)n * HW + hw0 + i) * C2 + c0 + tx];
    __syncthreads();
#pragma unroll
    for (int i = ty; i < 32; i += 8) {
        int c = c0 + i, hw = hw0 + tx;
        float v = t[tx][i];
        float s = g[c] * rsqrtf(1.0f + BN_EPS);
        v = silu(fmaf(v, s, b[c]));
        size_t idx = ((size_t)n * C2 + c) * HW + hw;
        out[idx] = xres[idx] + v;
    }
}

// ---------------------------------------------------------------------------
// Launch
// ---------------------------------------------------------------------------
extern "C" void kernel_launch(void* const* d_in, const int* in_sizes, int n_in,
                              void* d_out, int out_size) {
    const float* x     = (const float*)d_in[0];
    const float* cv1_w = (const float*)d_in[1];
    const float* cv1_g = (const float*)d_in[2];
    const float* cv1_b = (const float*)d_in[3];
    const float* pw_w  = (const float*)d_in[4];
    const float* pw_g  = (const float*)d_in[5];
    const float* pw_b  = (const float*)d_in[6];
    const float* dw_w  = (const float*)d_in[7];
    const float* dw_b  = (const float*)d_in[8];
    const float* ln_g  = (const float*)d_in[9];
    const float* ln_b  = (const float*)d_in[10];
    const float* off_w = (const float*)d_in[11];
    const float* off_b = (const float*)d_in[12];
    const float* msk_w = (const float*)d_in[13];
    const float* msk_b = (const float*)d_in[14];
    const float* inp_w = (const float*)d_in[15];
    const float* inp_b = (const float*)d_in[16];
    const float* out_w = (const float*)d_in[17];
    const float* out_b = (const float*)d_in[18];
    const float* bn2_g = (const float*)d_in[19];
    const float* bn2_b = (const float*)d_in[20];

    float* sc = nullptr;
    cudaGetSymbolAddress((void**)&sc, g_scratch);
    hlf* xhi  = (hlf*)(sc + OFF_XHI);
    hlf* y1hi = (hlf*)(sc + OFF_Y1HI);
    hlf* y2hi = (hlf*)(sc + OFF_Y2HI);
    hlf* x1hi = (hlf*)(sc + OFF_X1HI);
    hlf* xprojh = (hlf*)(sc + OFF_XPROJ);
    float* om    = sc + OFF_OM;
    hlf* chi  = (hlf*)(sc + OFF_CHI);
    float* onh = sc + OFF_ONH;
    hlf* vbuf = (hlf*)(sc + OFF_VBUF);
    hlf* mbuf = (hlf*)(sc + OFF_MBUF);
    hlf* uw   = (hlf*)(sc + OFF_UW);
    hlf* pwh  = (hlf*)(sc + OFF_PWH);
    hlf* inh  = (hlf*)(sc + OFF_INH);
    hlf* ouh  = (hlf*)(sc + OFF_OUH);
    hlf* hwh  = (hlf*)(sc + OFF_HWH);
    float* hb = sc + OFF_HB;
    float* outp = (float*)d_out;

    cudaFuncSetAttribute(wino_gemm_k, cudaFuncAttributeMaxDynamicSharedMemorySize, GEMM_SMEM1);
    cudaFuncSetAttribute(mma_gemm_nl_k, cudaFuncAttributeMaxDynamicSharedMemorySize, GEMM_SMEM1);
    cudaFuncSetAttribute(mma_gemm_k<1>, cudaFuncAttributeMaxDynamicSharedMemorySize, GEMM_SMEM1);
    cudaFuncSetAttribute(mma_gemm_k<2>, cudaFuncAttributeMaxDynamicSharedMemorySize, GEMM_SMEM1);
    cudaFuncSetAttribute(mma_head_k, cudaFuncAttributeMaxDynamicSharedMemorySize, HEAD_SMEM);

    // 0) preprocessing
    prep_x_k<<<dim3(HW / 32, C1 / 32, NB), 256>>>(x, xhi);
    int prep_tot = C2 * CM + 2 * C2 * C2 + 32 * C2 + 32;
    prep_w_k<<<(prep_tot + 255) / 256, 256>>>(
        pw_w, inp_w, out_w, off_w, msk_w, off_b, msk_b,
        pwh, inh, ouh, hwh, hb);
    wino_w_k<<<(CM * C1 + 255) / 256, 256>>>(cv1_w, uw);

    // 1) cv1 via Winograd F(2x2,3x3)
    wino_inp_k<<<NTILES / 2, 256>>>(xhi, vbuf);
    wino_gemm_k<<<dim3(NTILES / 64, 16), 256, GEMM_SMEM1>>>(vbuf, uw, mbuf);
    wino_out_k<<<NTILES / 4, 256>>>(mbuf, cv1_g, cv1_b, y1hi);

    // 2) pw (1-term, N-loop) -> y2hi
    mma_gemm_nl_k<<<NPIX / 64, 256, GEMM_SMEM1>>>(y1hi, pwh, pw_g, pw_b, y2hi);

    // 3) dw (half2) + LN + GELU -> x1hi
    dw_ln_gelu_k<<<NPIX, 128>>>(y2hi, dw_w, dw_b, ln_g, ln_b, x1hi);

    // 4) offset/mask heads -> om (logits)
    mma_head_k<<<NPIX / 128, 256, HEAD_SMEM>>>(x1hi, hwh, hb, om);

    // 5) input_proj (1-term) -> xproj fp16
    mma_gemm_k<2><<<dim3(NPIX / 64, 2), 256, GEMM_SMEM1>>>(
        y2hi, inh, inp_b, nullptr, xprojh);

    // 6) DCNv3 core (half2, softmax inside) -> chi fp16
    dcnv3_k<<<NPIX, 128>>>(xprojh, om, chi);

    // 7) output_proj (1-term) + bias -> onh f32 NHWC
    mma_gemm_k<1><<<dim3(NPIX / 64, 2), 256, GEMM_SMEM1>>>(
        chi, ouh, out_b, onh, nullptr);

    // 8) BN2 + SiLU + residual + transpose -> d_out NCHW
    bn2_res_transpose_k<<<dim3(HW / 32, C2 / 32, NB), 256>>>(onh, x, bn2_g, bn2_b, outp);
}